// round 3
// baseline (speedup 1.0000x reference)
#include <cuda_runtime.h>
#include <cuda_bf16.h>

#define Nn 128
#define Dd 256
#define Tt 512
#define NT 256
#define Bb 512

// dynamic smem layout (floats):
//  adj_s : 128*128         (reused as x-tile in phase 7)
//  S_s   : 128*128
//  U_s   : 128*128
//  w_s   : 256
//  d_s   : 128   (deg^-1/2)
//  mk_s  : 128   (row mask 0/1)
//  t_s   : 128   (y*d, later reused as row scale for S)
//  al_s  : 128   (alpha)
//  dc_s  : 128   (d_j * cut_alpha_j)
//  misc  : 4     ([0]=idx, [1]=use_cut, [2]=cut)
//  pres  : 128 ints
#define SMEM_FLOATS (3*Nn*Nn + Dd + 6*Nn + 4 + Nn)
#define SMEM_BYTES  (SMEM_FLOATS * 4)

__global__ __launch_bounds__(NT, 1)
void graph_enc_kernel(const float* __restrict__ x_g,
                      const float* __restrict__ adj_g,
                      const int*   __restrict__ head_g,
                      const float* __restrict__ w_g,
                      const float* __restrict__ bias_g,
                      float* __restrict__ emb_out,
                      float* __restrict__ adj_out)
{
    const int b = blockIdx.x;
    extern __shared__ float sm[];
    float* adj_s = sm;
    float* S_s   = sm + Nn*Nn;
    float* U_s   = sm + 2*Nn*Nn;
    float* w_s   = sm + 3*Nn*Nn;
    float* d_s   = w_s + Dd;
    float* mk_s  = d_s + Nn;
    float* t_s   = mk_s + Nn;
    float* al_s  = t_s + Nn;
    float* dc_s  = al_s + Nn;
    float* misc  = dc_s + Nn;
    int*   pres  = (int*)(misc + 4);

    const int tid  = threadIdx.x;
    const int lane = tid & 31;
    const int warp = tid >> 5;      // 8 warps
    const int tx   = tid & 15;      // 16x16 thread grid for matmuls
    const int ty   = tid >> 4;

    const float* adj_b = adj_g + (size_t)b * Nn * Nn;
    const float* x_b   = x_g   + (size_t)b * Nn * Dd;

    // ---- load adj, w, clear presence ----
    {
        const float4* a4  = (const float4*)adj_b;
        float4*       as4 = (float4*)adj_s;
        #pragma unroll
        for (int i = tid; i < Nn*Nn/4; i += NT) as4[i] = a4[i];
    }
    w_s[tid] = w_g[tid];            // NT == Dd == 256
    if (tid < Nn) pres[tid] = 0;
    __syncthreads();

    // ---- presence marks (T = 512 = 2*NT) ----
    {
        const int* hb = head_g + (size_t)b * Tt;
        pres[hb[tid]]      = 1;
        pres[hb[tid + NT]] = 1;
    }

    // ---- row sums -> d_i = rsqrt(max(rs+1,1)), mask_i = rs>0 ----
    for (int r = 0; r < 16; r++) {
        int i = warp * 16 + r;
        float s = 0.f;
        #pragma unroll
        for (int j = lane; j < Nn; j += 32) s += adj_s[i*Nn + j];
        #pragma unroll
        for (int o = 16; o; o >>= 1) s += __shfl_xor_sync(0xffffffffu, s, o);
        if (lane == 0) {
            float deg = s + 1.0f;
            if (deg < 1.0f) deg = 1.0f;
            d_s[i]  = rsqrtf(deg);
            mk_s[i] = (s > 0.0f) ? 1.0f : 0.0f;
        }
    }
    __syncthreads();

    // ---- t_i = (x_i . w) * d_i ----
    for (int r = 0; r < 16; r++) {
        int i = warp * 16 + r;
        float s = 0.f;
        const float* xr = x_b + (size_t)i * Dd;
        #pragma unroll
        for (int j = lane; j < Dd; j += 32) s += xr[j] * w_s[j];
        #pragma unroll
        for (int o = 16; o; o >>= 1) s += __shfl_xor_sync(0xffffffffu, s, o);
        if (lane == 0) t_s[i] = s * d_s[i];
    }
    __syncthreads();

    // ---- z_i = m_i d_i (adj_i . t + t_i) + bias ; alpha = sigmoid(z^2) ----
    {
        float bias = __ldg(bias_g);
        for (int r = 0; r < 16; r++) {
            int i = warp * 16 + r;
            float s = 0.f;
            #pragma unroll
            for (int j = lane; j < Nn; j += 32) s += adj_s[i*Nn + j] * t_s[j];
            #pragma unroll
            for (int o = 16; o; o >>= 1) s += __shfl_xor_sync(0xffffffffu, s, o);
            if (lane == 0) {
                float z  = mk_s[i] * d_s[i] * (s + t_s[i]) + bias;
                float zz = z * z;
                al_s[i] = 1.0f / (1.0f + expf(-zz));
            }
        }
    }
    __syncthreads();

    // ---- unique count -> k, idx ----
    if (warp == 0) {
        int c = pres[lane] + pres[lane+32] + pres[lane+64] + pres[lane+96];
        #pragma unroll
        for (int o = 16; o; o >>= 1) c += __shfl_xor_sync(0xffffffffu, c, o);
        if (lane == 0) {
            int k = (int)ceilf((float)c * 0.1f) + 1;   // bit-exact vs fp32 ref
            int idx = k - 1;
            if (idx > Nn - 1) idx = Nn - 1;
            if (idx < 0) idx = 0;
            misc[0] = (float)idx;
            misc[1] = (c > 1) ? 1.0f : 0.0f;
        }
    }
    __syncthreads();

    // ---- cut = idx-th (0-based) largest alpha, tie-correct rank select ----
    if (tid < Nn) {
        float a = al_s[tid];
        int rk = 0, eq = 0;
        #pragma unroll 4
        for (int j = 0; j < Nn; j++) {
            float aj = al_s[j];
            rk += (aj > a);
            eq += (aj == a);
        }
        int idx = (int)misc[0];
        if (rk <= idx && idx < rk + eq) misc[2] = a;
    }
    __syncthreads();

    // ---- dc_j = d_j * relu(alpha_j + 1e-7 - cut) ----
    if (tid < Nn) {
        float cut = (misc[1] != 0.0f) ? misc[2] : 0.0f;
        float ca = al_s[tid] + 1e-7f - cut;
        if (ca < 0.f) ca = 0.f;
        dc_s[tid] = ca * d_s[tid];
    }
    __syncthreads();

    // ---- S row sums -> per-row scale (reuse t_s) ----
    for (int r = 0; r < 16; r++) {
        int i = warp * 16 + r;
        float s = 0.f;
        #pragma unroll
        for (int j = lane; j < Nn; j += 32) {
            float a = adj_s[i*Nn + j] + ((i == j) ? 1.0f : 0.0f);
            s += a * dc_s[j];
        }
        #pragma unroll
        for (int o = 16; o; o >>= 1) s += __shfl_xor_sync(0xffffffffu, s, o);
        if (lane == 0) {
            float md  = mk_s[i] * d_s[i];
            float den = md * s;
            if (den < 1e-12f) den = 1e-12f;
            t_s[i] = md / den;   // S_ij = t_s[i] * A_ij * dc_j
        }
    }
    __syncthreads();

    // ---- fill S ----
    {
        int j  = tid & 127;
        int i0 = tid >> 7;
        for (int i = i0; i < Nn; i += 2) {
            float a = adj_s[i*Nn + j] + ((i == j) ? 1.0f : 0.0f);
            S_s[i*Nn + j] = t_s[i] * a * dc_s[j];
        }
    }
    __syncthreads();

    // ---- matmul 1: U = adj @ S ----
    {
        float acc[8][8];
        #pragma unroll
        for (int a = 0; a < 8; a++)
            #pragma unroll
            for (int m = 0; m < 8; m++) acc[a][m] = 0.f;

        for (int k = 0; k < Nn; k++) {
            float ar[8], br[8];
            #pragma unroll
            for (int a = 0; a < 8; a++) ar[a] = adj_s[(ty + 16*a)*Nn + k];
            #pragma unroll
            for (int m = 0; m < 8; m++) br[m] = S_s[k*Nn + tx + 16*m];
            #pragma unroll
            for (int a = 0; a < 8; a++)
                #pragma unroll
                for (int m = 0; m < 8; m++) acc[a][m] += ar[a] * br[m];
        }
        #pragma unroll
        for (int a = 0; a < 8; a++)
            #pragma unroll
            for (int m = 0; m < 8; m++)
                U_s[(ty + 16*a)*Nn + tx + 16*m] = acc[a][m];
    }
    __syncthreads();

    // ---- matmul 2: new_adj = S^T @ U -> global ----
    {
        float acc[8][8];
        #pragma unroll
        for (int a = 0; a < 8; a++)
            #pragma unroll
            for (int m = 0; m < 8; m++) acc[a][m] = 0.f;

        for (int k = 0; k < Nn; k++) {
            float sr[8], ur[8];
            #pragma unroll
            for (int a = 0; a < 8; a++) sr[a] = S_s[k*Nn + ty + 16*a];
            #pragma unroll
            for (int m = 0; m < 8; m++) ur[m] = U_s[k*Nn + tx + 16*m];
            #pragma unroll
            for (int a = 0; a < 8; a++)
                #pragma unroll
                for (int m = 0; m < 8; m++) acc[a][m] += sr[a] * ur[m];
        }
        float* ob = adj_out + (size_t)b * Nn * Nn;
        #pragma unroll
        for (int a = 0; a < 8; a++)
            #pragma unroll
            for (int m = 0; m < 8; m++)
                ob[(ty + 16*a)*Nn + tx + 16*m] = acc[a][m];
    }

    // ---- phase 7: emb = S^T @ x, two 128-wide d-tiles (reuse adj_s as x tile) ----
    float* xs = adj_s;
    for (int tile = 0; tile < 2; tile++) {
        __syncthreads();   // prior readers of xs/adj_s done
        {
            const float4* xb4 = (const float4*)x_b;
            float4*       xs4 = (float4*)xs;
            #pragma unroll
            for (int lnr = tid; lnr < Nn*32; lnr += NT) {
                int i  = lnr >> 5;         // row
                int c4 = lnr & 31;         // float4 col within tile
                xs4[i*32 + c4] = xb4[i*64 + tile*32 + c4];
            }
        }
        __syncthreads();

        float acc[8][8];
        #pragma unroll
        for (int a = 0; a < 8; a++)
            #pragma unroll
            for (int m = 0; m < 8; m++) acc[a][m] = 0.f;

        for (int k = 0; k < Nn; k++) {
            float sr[8], xr[8];
            #pragma unroll
            for (int a = 0; a < 8; a++) sr[a] = S_s[k*Nn + ty + 16*a];
            #pragma unroll
            for (int m = 0; m < 8; m++) xr[m] = xs[k*Nn + tx + 16*m];
            #pragma unroll
            for (int a = 0; a < 8; a++)
                #pragma unroll
                for (int m = 0; m < 8; m++) acc[a][m] += sr[a] * xr[m];
        }
        float* ob = emb_out + (size_t)b * Nn * Dd + tile * 128;
        #pragma unroll
        for (int a = 0; a < 8; a++)
            #pragma unroll
            for (int m = 0; m < 8; m++)
                ob[(ty + 16*a)*Dd + tx + 16*m] = acc[a][m];
    }
}

extern "C" void kernel_launch(void* const* d_in, const int* in_sizes, int n_in,
                              void* d_out, int out_size) {
    const float* x    = (const float*)d_in[0];
    const float* adj  = (const float*)d_in[1];
    const int*   head = (const int*)d_in[2];
    const float* w    = (const float*)d_in[3];
    const float* bias = (const float*)d_in[4];

    float* out  = (float*)d_out;
    float* emb  = out;                                  // [B,N,D]
    float* nadj = out + (size_t)Bb * Nn * Dd;           // [B,N,N]

    cudaFuncSetAttribute(graph_enc_kernel,
                         cudaFuncAttributeMaxDynamicSharedMemorySize, SMEM_BYTES);
    graph_enc_kernel<<<Bb, NT, SMEM_BYTES>>>(x, adj, head, w, bias, emb, nadj);
}

// round 5
// speedup vs baseline: 1.5760x; 1.5760x over previous
#include <cuda_runtime.h>
#include <cuda_bf16.h>

#define Nn 128
#define Dd 256
#define Tt 512
#define NT 256
#define Bb 512

// dynamic smem layout (floats):
//  adj_s : 128*128         (reused as x-tile in phase 7)
//  S_s   : 128*128
//  U_s   : 128*128
//  w_s   : 256
//  d_s   : 128   (deg^-1/2)
//  mk_s  : 128   (row mask 0/1)
//  t_s   : 128   (y*d, later reused as row scale for S)
//  al_s  : 128   (alpha)
//  dc_s  : 128   (d_j * cut_alpha_j)
//  misc  : 4     ([0]=idx, [1]=use_cut, [2]=cut)
//  pres  : 128 ints
#define SMEM_FLOATS (3*Nn*Nn + Dd + 6*Nn + 4 + Nn)
#define SMEM_BYTES  (SMEM_FLOATS * 4)

__global__ __launch_bounds__(NT, 1)
void graph_enc_kernel(const float* __restrict__ x_g,
                      const float* __restrict__ adj_g,
                      const int*   __restrict__ head_g,
                      const float* __restrict__ w_g,
                      const float* __restrict__ bias_g,
                      float* __restrict__ emb_out,
                      float* __restrict__ adj_out)
{
    const int b = blockIdx.x;
    extern __shared__ float sm[];
    float* adj_s = sm;
    float* S_s   = sm + Nn*Nn;
    float* U_s   = sm + 2*Nn*Nn;
    float* w_s   = sm + 3*Nn*Nn;
    float* d_s   = w_s + Dd;
    float* mk_s  = d_s + Nn;
    float* t_s   = mk_s + Nn;
    float* al_s  = t_s + Nn;
    float* dc_s  = al_s + Nn;
    float* misc  = dc_s + Nn;
    int*   pres  = (int*)(misc + 4);

    const int tid  = threadIdx.x;
    const int lane = tid & 31;
    const int warp = tid >> 5;      // 8 warps
    const int tx   = tid & 15;      // 16x16 thread grid for matmuls
    const int ty   = tid >> 4;

    const float* adj_b = adj_g + (size_t)b * Nn * Nn;
    const float* x_b   = x_g   + (size_t)b * Nn * Dd;

    // ---- load adj, w, clear presence ----
    {
        const float4* a4  = (const float4*)adj_b;
        float4*       as4 = (float4*)adj_s;
        #pragma unroll
        for (int i = tid; i < Nn*Nn/4; i += NT) as4[i] = a4[i];
    }
    w_s[tid] = w_g[tid];            // NT == Dd == 256
    if (tid < Nn) pres[tid] = 0;
    __syncthreads();

    // ---- presence marks (T = 512 = 2*NT) ----
    {
        const int* hb = head_g + (size_t)b * Tt;
        pres[hb[tid]]      = 1;
        pres[hb[tid + NT]] = 1;
    }

    // ---- row sums -> d_i = rsqrt(max(rs+1,1)), mask_i = rs>0 ----
    for (int r = 0; r < 16; r++) {
        int i = warp * 16 + r;
        float s = 0.f;
        #pragma unroll
        for (int j = lane; j < Nn; j += 32) s += adj_s[i*Nn + j];
        #pragma unroll
        for (int o = 16; o; o >>= 1) s += __shfl_xor_sync(0xffffffffu, s, o);
        if (lane == 0) {
            float deg = s + 1.0f;
            if (deg < 1.0f) deg = 1.0f;
            d_s[i]  = rsqrtf(deg);
            mk_s[i] = (s > 0.0f) ? 1.0f : 0.0f;
        }
    }
    __syncthreads();

    // ---- t_i = (x_i . w) * d_i ----
    for (int r = 0; r < 16; r++) {
        int i = warp * 16 + r;
        float s = 0.f;
        const float* xr = x_b + (size_t)i * Dd;
        #pragma unroll
        for (int j = lane; j < Dd; j += 32) s += xr[j] * w_s[j];
        #pragma unroll
        for (int o = 16; o; o >>= 1) s += __shfl_xor_sync(0xffffffffu, s, o);
        if (lane == 0) t_s[i] = s * d_s[i];
    }
    __syncthreads();

    // ---- z_i = m_i d_i (adj_i . t + t_i) + bias ; alpha = sigmoid(z^2) ----
    {
        float bias = __ldg(bias_g);
        for (int r = 0; r < 16; r++) {
            int i = warp * 16 + r;
            float s = 0.f;
            #pragma unroll
            for (int j = lane; j < Nn; j += 32) s += adj_s[i*Nn + j] * t_s[j];
            #pragma unroll
            for (int o = 16; o; o >>= 1) s += __shfl_xor_sync(0xffffffffu, s, o);
            if (lane == 0) {
                float z  = mk_s[i] * d_s[i] * (s + t_s[i]) + bias;
                float zz = z * z;
                al_s[i] = 1.0f / (1.0f + expf(-zz));
            }
        }
    }
    __syncthreads();

    // ---- unique count -> k, idx ----
    if (warp == 0) {
        int c = pres[lane] + pres[lane+32] + pres[lane+64] + pres[lane+96];
        #pragma unroll
        for (int o = 16; o; o >>= 1) c += __shfl_xor_sync(0xffffffffu, c, o);
        if (lane == 0) {
            int k = (int)ceilf((float)c * 0.1f) + 1;   // bit-exact vs fp32 ref
            int idx = k - 1;
            if (idx > Nn - 1) idx = Nn - 1;
            if (idx < 0) idx = 0;
            misc[0] = (float)idx;
            misc[1] = (c > 1) ? 1.0f : 0.0f;
        }
    }
    __syncthreads();

    // ---- cut = idx-th (0-based) largest alpha, tie-correct rank select ----
    if (tid < Nn) {
        float a = al_s[tid];
        int rk = 0, eq = 0;
        #pragma unroll 4
        for (int j = 0; j < Nn; j++) {
            float aj = al_s[j];
            rk += (aj > a);
            eq += (aj == a);
        }
        int idx = (int)misc[0];
        if (rk <= idx && idx < rk + eq) misc[2] = a;
    }
    __syncthreads();

    // ---- dc_j = d_j * relu(alpha_j + 1e-7 - cut) ----
    if (tid < Nn) {
        float cut = (misc[1] != 0.0f) ? misc[2] : 0.0f;
        float ca = al_s[tid] + 1e-7f - cut;
        if (ca < 0.f) ca = 0.f;
        dc_s[tid] = ca * d_s[tid];
    }
    __syncthreads();

    // ---- S row sums -> per-row scale (reuse t_s) ----
    for (int r = 0; r < 16; r++) {
        int i = warp * 16 + r;
        float s = 0.f;
        #pragma unroll
        for (int j = lane; j < Nn; j += 32) {
            float a = adj_s[i*Nn + j] + ((i == j) ? 1.0f : 0.0f);
            s += a * dc_s[j];
        }
        #pragma unroll
        for (int o = 16; o; o >>= 1) s += __shfl_xor_sync(0xffffffffu, s, o);
        if (lane == 0) {
            float md  = mk_s[i] * d_s[i];
            float den = md * s;
            if (den < 1e-12f) den = 1e-12f;
            t_s[i] = md / den;   // S_ij = t_s[i] * A_ij * dc_j
        }
    }
    __syncthreads();

    // ---- fill S ----
    {
        int j  = tid & 127;
        int i0 = tid >> 7;
        for (int i = i0; i < Nn; i += 2) {
            float a = adj_s[i*Nn + j] + ((i == j) ? 1.0f : 0.0f);
            S_s[i*Nn + j] = t_s[i] * a * dc_s[j];
        }
    }
    __syncthreads();

    // ---- matmul 1: U = adj @ S ----
    {
        float acc[8][8];
        #pragma unroll
        for (int a = 0; a < 8; a++)
            #pragma unroll
            for (int m = 0; m < 8; m++) acc[a][m] = 0.f;

        for (int k = 0; k < Nn; k++) {
            float ar[8], br[8];
            #pragma unroll
            for (int a = 0; a < 8; a++) ar[a] = adj_s[(ty + 16*a)*Nn + k];
            #pragma unroll
            for (int m = 0; m < 8; m++) br[m] = S_s[k*Nn + tx + 16*m];
            #pragma unroll
            for (int a = 0; a < 8; a++)
                #pragma unroll
                for (int m = 0; m < 8; m++) acc[a][m] += ar[a] * br[m];
        }
        #pragma unroll
        for (int a = 0; a < 8; a++)
            #pragma unroll
            for (int m = 0; m < 8; m++)
                U_s[(ty + 16*a)*Nn + tx + 16*m] = acc[a][m];
    }
    __syncthreads();

    // ---- matmul 2: new_adj = S^T @ U -> global ----
    {
        float acc[8][8];
        #pragma unroll
        for (int a = 0; a < 8; a++)
            #pragma unroll
            for (int m = 0; m < 8; m++) acc[a][m] = 0.f;

        for (int k = 0; k < Nn; k++) {
            float sr[8], ur[8];
            #pragma unroll
            for (int a = 0; a < 8; a++) sr[a] = S_s[k*Nn + ty + 16*a];
            #pragma unroll
            for (int m = 0; m < 8; m++) ur[m] = U_s[k*Nn + tx + 16*m];
            #pragma unroll
            for (int a = 0; a < 8; a++)
                #pragma unroll
                for (int m = 0; m < 8; m++) acc[a][m] += sr[a] * ur[m];
        }
        float* ob = adj_out + (size_t)b * Nn * Nn;
        #pragma unroll
        for (int a = 0; a < 8; a++)
            #pragma unroll
            for (int m = 0; m < 8; m++)
                ob[(ty + 16*a)*Nn + tx + 16*m] = acc[a][m];
    }

    // ---- phase 7: emb = S^T @ x, two 128-wide d-tiles (reuse adj_s as x tile) ----
    float* xs = adj_s;
    for (int tile = 0; tile < 2; tile++) {
        __syncthreads();   // prior readers of xs/adj_s done
        {
            const float4* xb4 = (const float4*)x_b;
            float4*       xs4 = (float4*)xs;
            #pragma unroll
            for (int lnr = tid; lnr < Nn*32; lnr += NT) {
                int i  = lnr >> 5;         // row
                int c4 = lnr & 31;         // float4 col within tile
                xs4[i*32 + c4] = xb4[i*64 + tile*32 + c4];
            }
        }
        __syncthreads();

        float acc[8][8];
        #pragma unroll
        for (int a = 0; a < 8; a++)
            #pragma unroll
            for (int m = 0; m < 8; m++) acc[a][m] = 0.f;

        for (int k = 0; k < Nn; k++) {
            float sr[8], xr[8];
            #pragma unroll
            for (int a = 0; a < 8; a++) sr[a] = S_s[k*Nn + ty + 16*a];
            #pragma unroll
            for (int m = 0; m < 8; m++) xr[m] = xs[k*Nn + tx + 16*m];
            #pragma unroll
            for (int a = 0; a < 8; a++)
                #pragma unroll
                for (int m = 0; m < 8; m++) acc[a][m] += sr[a] * xr[m];
        }
        float* ob = emb_out + (size_t)b * Nn * Dd + tile * 128;
        #pragma unroll
        for (int a = 0; a < 8; a++)
            #pragma unroll
            for (int m = 0; m < 8; m++)
                ob[(ty + 16*a)*Dd + tx + 16*m] = acc[a][m];
    }
}

extern "C" void kernel_launch(void* const* d_in, const int* in_sizes, int n_in,
                              void* d_out, int out_size) {
    const float* x    = (const float*)d_in[0];
    const float* adj  = (const float*)d_in[1];
    const int*   head = (const int*)d_in[2];
    const float* w    = (const float*)d_in[3];
    const float* bias = (const float*)d_in[4];

    float* out  = (float*)d_out;
    float* emb  = out;                                  // [B,N,D]
    float* nadj = out + (size_t)Bb * Nn * Dd;           // [B,N,N]

    cudaFuncSetAttribute(graph_enc_kernel,
                         cudaFuncAttributeMaxDynamicSharedMemorySize, SMEM_BYTES);
    graph_enc_kernel<<<Bb, NT, SMEM_BYTES>>>(x, adj, head, w, bias, emb, nadj);
}

// round 10
// speedup vs baseline: 3.4528x; 2.1909x over previous
#include <cuda_runtime.h>
#include <cuda_bf16.h>
#include <cstdint>

#define Nn 128
#define Dd 256
#define Tt 512
#define NT 512
#define Bb 512
#define PAD 129

#define STRB 272              // bytes per row of a bf16 operand tile (136 bf16)
#define TILEB 34816           // 128 * 272 bytes per tile (hi or lo)

// ---- dynamic smem byte offsets ----
#define OFF_STAGE 0           // 128*129*4 = 66048 B fp32 stage (adj -> U -> x)
#define OFF_W     66048
#define OFF_D     67072
#define OFF_MK    67584
#define OFF_T     68096
#define OFF_AL    68608
#define OFF_DC    69120
#define OFF_MISC  69632
#define OFF_PRES  69696
#define OFF_R1    70208       // A-side tiles: hi @ +0, lo @ +TILEB  (adj -> Ut -> xt)
#define OFF_R2    139840      // P = S^T tiles: hi/lo
#define SMEM_BYTES 209472

// ---------------- helpers ----------------
__device__ __forceinline__ uint32_t smem_u32(const void* p) {
    uint32_t a;
    asm("{ .reg .u64 t; cvta.to.shared.u64 t, %1; cvt.u32.u64 %0, t; }" : "=r"(a) : "l"(p));
    return a;
}

__device__ __forceinline__ void ldsm4(uint32_t* r, uint32_t addr) {
    asm volatile("ldmatrix.sync.aligned.m8n8.x4.shared.b16 {%0,%1,%2,%3}, [%4];"
        : "=r"(r[0]), "=r"(r[1]), "=r"(r[2]), "=r"(r[3]) : "r"(addr));
}

__device__ __forceinline__ void mma_bf16(float* d, const uint32_t* a, const uint32_t* b) {
    asm volatile(
        "mma.sync.aligned.m16n8k16.row.col.f32.bf16.bf16.f32 "
        "{%0,%1,%2,%3}, {%4,%5,%6,%7}, {%8,%9}, {%0,%1,%2,%3};"
        : "+f"(d[0]), "+f"(d[1]), "+f"(d[2]), "+f"(d[3])
        : "r"(a[0]), "r"(a[1]), "r"(a[2]), "r"(a[3]), "r"(b[0]), "r"(b[1]));
}

__device__ __forceinline__ void split_pair(float v0, float v1, uint32_t& h, uint32_t& l) {
    __nv_bfloat16 h0 = __float2bfloat16(v0);
    __nv_bfloat16 h1 = __float2bfloat16(v1);
    __nv_bfloat16 l0 = __float2bfloat16(v0 - __bfloat162float(h0));
    __nv_bfloat16 l1 = __float2bfloat16(v1 - __bfloat162float(h1));
    h = (uint32_t)__bfloat16_as_ushort(h0) | ((uint32_t)__bfloat16_as_ushort(h1) << 16);
    l = (uint32_t)__bfloat16_as_ushort(l0) | ((uint32_t)__bfloat16_as_ushort(l1) << 16);
}

// 3-term-split 128x128x128 GEMM piece: warp computes its 32x32 output tile.
// A tile at aBase (row-major [m][k] bf16, hi @ +0, lo @ +TILEB, row stride STRB)
// B^T tile at bBase (row-major [n][k], same layout). acc[32] accumulates fp32.
__device__ __forceinline__ void warp_gemm3(uint32_t aBase, uint32_t bBase,
                                           int m0, int n0, int lane, float* acc)
{
    const uint32_t aRow = (uint32_t)(lane & 15);
    const uint32_t aK   = (uint32_t)((lane >> 4) << 4);                 // +8 bf16 = 16B
    const uint32_t bRow = (uint32_t)((lane & 7) + ((lane >> 4) << 3));
    const uint32_t bK   = (uint32_t)(((lane >> 3) & 1) << 4);

    const uint32_t a0 = aBase + (uint32_t)(m0 + aRow) * STRB + aK;
    const uint32_t a1 = a0 + 16u * STRB;
    const uint32_t b0 = bBase + (uint32_t)(n0 + bRow) * STRB + bK;
    const uint32_t b1 = b0 + 16u * STRB;

    #pragma unroll
    for (int ks = 0; ks < 8; ks++) {
        const uint32_t ko = (uint32_t)ks * 32u;     // 16 bf16 = 32 bytes per k-step
        uint32_t Ah[2][4], Al[2][4], Bh[2][4], Bl[2][4];
        ldsm4(Ah[0], a0 + ko);
        ldsm4(Ah[1], a1 + ko);
        ldsm4(Bh[0], b0 + ko);
        ldsm4(Bh[1], b1 + ko);
        ldsm4(Al[0], a0 + TILEB + ko);
        ldsm4(Al[1], a1 + TILEB + ko);
        ldsm4(Bl[0], b0 + TILEB + ko);
        ldsm4(Bl[1], b1 + TILEB + ko);
        #pragma unroll
        for (int mf = 0; mf < 2; mf++) {
            #pragma unroll
            for (int nf = 0; nf < 4; nf++) {
                float* c = acc + (mf * 4 + nf) * 4;
                const uint32_t* bhp = &Bh[nf >> 1][(nf & 1) * 2];
                const uint32_t* blp = &Bl[nf >> 1][(nf & 1) * 2];
                mma_bf16(c, Ah[mf], bhp);   // hi*hi
                mma_bf16(c, Ah[mf], blp);   // hi*lo
                mma_bf16(c, Al[mf], bhp);   // lo*hi
            }
        }
    }
}

__global__ __launch_bounds__(NT, 1)
void graph_enc_tc(const float* __restrict__ x_g,
                  const float* __restrict__ adj_g,
                  const int*   __restrict__ head_g,
                  const float* __restrict__ w_g,
                  const float* __restrict__ bias_g,
                  float* __restrict__ emb_out,
                  float* __restrict__ adj_out)
{
    const int b = blockIdx.x;
    extern __shared__ char smc[];
    const uint32_t sb = smem_u32(smc);

    float* stage = (float*)(smc + OFF_STAGE);
    float* wv    = (float*)(smc + OFF_W);
    float* dv    = (float*)(smc + OFF_D);
    float* mk    = (float*)(smc + OFF_MK);
    float* tv    = (float*)(smc + OFF_T);
    float* al    = (float*)(smc + OFF_AL);
    float* dc    = (float*)(smc + OFF_DC);
    float* misc  = (float*)(smc + OFF_MISC);
    int*   pres  = (int*)(smc + OFF_PRES);

    const int tid  = threadIdx.x;
    const int lane = tid & 31;
    const int wid  = tid >> 5;              // 16 warps
    const int m0   = (wid >> 2) * 32;       // warp tile origin in 4x4 grid
    const int n0   = (wid & 3) * 32;
    const int gid  = lane >> 2;
    const int tig  = lane & 3;

    const float* adj_b = adj_g + (size_t)b * Nn * Nn;
    const float* x_b   = x_g   + (size_t)b * Nn * Dd;

    // ---- load adj into padded fp32 stage; w; clear presence ----
    {
        const float4* a4 = (const float4*)adj_b;
        for (int p = tid; p < Nn * 32; p += NT) {
            int r = p >> 5, q = p & 31;
            float4 v = a4[r * 32 + q];
            float* d = stage + r * PAD + q * 4;
            d[0] = v.x; d[1] = v.y; d[2] = v.z; d[3] = v.w;
        }
    }
    if (tid < Dd) wv[tid] = w_g[tid];
    if (tid < Nn) pres[tid] = 0;
    __syncthreads();

    // ---- presence marks (T == NT) ----
    pres[head_g[(size_t)b * Tt + tid]] = 1;

    // ---- row sums -> d_i, mask_i ----
    for (int rr = 0; rr < 8; rr++) {
        int i = wid * 8 + rr;
        const float* row = stage + i * PAD;
        float s = row[lane] + row[lane + 32] + row[lane + 64] + row[lane + 96];
        #pragma unroll
        for (int o = 16; o; o >>= 1) s += __shfl_xor_sync(0xffffffffu, s, o);
        if (lane == 0) {
            float deg = s + 1.0f;
            if (deg < 1.0f) deg = 1.0f;
            dv[i] = rsqrtf(deg);
            mk[i] = (s > 0.0f) ? 1.0f : 0.0f;
        }
    }
    __syncthreads();

    // ---- t_i = (x_i . w) * d_i ----
    for (int rr = 0; rr < 8; rr++) {
        int i = wid * 8 + rr;
        const float* xr = x_b + (size_t)i * Dd;
        float s = 0.f;
        #pragma unroll
        for (int j = lane; j < Dd; j += 32) s += xr[j] * wv[j];
        #pragma unroll
        for (int o = 16; o; o >>= 1) s += __shfl_xor_sync(0xffffffffu, s, o);
        if (lane == 0) tv[i] = s * dv[i];
    }
    __syncthreads();

    // ---- alpha ----
    {
        float bias = __ldg(bias_g);
        for (int rr = 0; rr < 8; rr++) {
            int i = wid * 8 + rr;
            const float* row = stage + i * PAD;
            float s = 0.f;
            #pragma unroll
            for (int j = lane; j < Nn; j += 32) s += row[j] * tv[j];
            #pragma unroll
            for (int o = 16; o; o >>= 1) s += __shfl_xor_sync(0xffffffffu, s, o);
            if (lane == 0) {
                float z  = mk[i] * dv[i] * (s + tv[i]) + bias;
                float zz = z * z;
                al[i] = 1.0f / (1.0f + expf(-zz));
            }
        }
    }
    __syncthreads();

    // ---- unique count -> idx, use_cut ----
    if (wid == 0) {
        int c = pres[lane] + pres[lane + 32] + pres[lane + 64] + pres[lane + 96];
        #pragma unroll
        for (int o = 16; o; o >>= 1) c += __shfl_xor_sync(0xffffffffu, c, o);
        if (lane == 0) {
            int k = (int)ceilf((float)c * 0.1f) + 1;
            int idx = k - 1;
            if (idx > Nn - 1) idx = Nn - 1;
            if (idx < 0) idx = 0;
            misc[0] = (float)idx;
            misc[1] = (c > 1) ? 1.0f : 0.0f;
        }
    }
    __syncthreads();

    // ---- rank-select cut (tie-correct) ----
    if (tid < Nn) {
        float a = al[tid];
        int rk = 0, eq = 0;
        #pragma unroll 4
        for (int j = 0; j < Nn; j++) {
            float aj = al[j];
            rk += (aj > a);
            eq += (aj == a);
        }
        int idx = (int)misc[0];
        if (rk <= idx && idx < rk + eq) misc[2] = a;
    }
    __syncthreads();

    // ---- dc_j = d_j * relu(alpha_j + 1e-7 - cut) ----
    if (tid < Nn) {
        float cut = (misc[1] != 0.0f) ? misc[2] : 0.0f;
        float ca = al[tid] + 1e-7f - cut;
        if (ca < 0.f) ca = 0.f;
        dc[tid] = ca * dv[tid];
    }
    __syncthreads();

    // ---- S row-scale -> tv ----
    for (int rr = 0; rr < 8; rr++) {
        int i = wid * 8 + rr;
        const float* row = stage + i * PAD;
        float s = 0.f;
        #pragma unroll
        for (int j = lane; j < Nn; j += 32) {
            float a = row[j] + ((i == j) ? 1.0f : 0.0f);
            s += a * dc[j];
        }
        #pragma unroll
        for (int o = 16; o; o >>= 1) s += __shfl_xor_sync(0xffffffffu, s, o);
        if (lane == 0) {
            float md  = mk[i] * dv[i];
            float den = md * s;
            if (den < 1e-12f) den = 1e-12f;
            tv[i] = md / den;          // S_ij = tv[i]*(A+I)_ij*dc[j]
        }
    }
    __syncthreads();

    // ---- build adj tiles (hi/lo) into R1; P = S^T into R2 ----
    for (int p = tid; p < 8192; p += NT) {
        int r = p >> 6, c = (p & 63) * 2;
        uint32_t h, l;
        split_pair(stage[r * PAD + c], stage[r * PAD + c + 1], h, l);
        uint32_t off = (uint32_t)r * STRB + (uint32_t)c * 2;
        *(uint32_t*)(smc + OFF_R1 + off)         = h;
        *(uint32_t*)(smc + OFF_R1 + TILEB + off) = l;
    }
    for (int p = tid; p < 8192; p += NT) {
        int r = p >> 6, c = (p & 63) * 2;   // P[r][c] = S[c][r]
        float a0 = stage[c * PAD + r]       + ((c == r)     ? 1.0f : 0.0f);
        float a1 = stage[(c + 1) * PAD + r] + ((c + 1 == r) ? 1.0f : 0.0f);
        float v0 = tv[c]     * a0 * dc[r];
        float v1 = tv[c + 1] * a1 * dc[r];
        uint32_t h, l;
        split_pair(v0, v1, h, l);
        uint32_t off = (uint32_t)r * STRB + (uint32_t)c * 2;
        *(uint32_t*)(smc + OFF_R2 + off)         = h;
        *(uint32_t*)(smc + OFF_R2 + TILEB + off) = l;
    }
    __syncthreads();

    // ---- GEMM1: U = adj @ S   (A = adj @ R1, B^T = P @ R2) -> stage ----
    {
        float acc[32];
        #pragma unroll
        for (int i = 0; i < 32; i++) acc[i] = 0.f;
        warp_gemm3(sb + OFF_R1, sb + OFF_R2, m0, n0, lane, acc);
        #pragma unroll
        for (int mf = 0; mf < 2; mf++)
            #pragma unroll
            for (int nf = 0; nf < 4; nf++) {
                const float* c4 = acc + (mf * 4 + nf) * 4;
                int r = m0 + mf * 16 + gid, c = n0 + nf * 8 + tig * 2;
                stage[r * PAD + c]           = c4[0];
                stage[r * PAD + c + 1]       = c4[1];
                stage[(r + 8) * PAD + c]     = c4[2];
                stage[(r + 8) * PAD + c + 1] = c4[3];
            }
    }
    __syncthreads();

    // ---- build Ut (hi/lo) into R1 ----
    for (int p = tid; p < 8192; p += NT) {
        int r = p >> 6, c = (p & 63) * 2;   // Ut[r][c] = U[c][r]
        uint32_t h, l;
        split_pair(stage[c * PAD + r], stage[(c + 1) * PAD + r], h, l);
        uint32_t off = (uint32_t)r * STRB + (uint32_t)c * 2;
        *(uint32_t*)(smc + OFF_R1 + off)         = h;
        *(uint32_t*)(smc + OFF_R1 + TILEB + off) = l;
    }
    __syncthreads();

    // ---- GEMM2: new_adj = S^T @ U  (A = P, B^T = Ut) -> gmem direct ----
    {
        float acc[32];
        #pragma unroll
        for (int i = 0; i < 32; i++) acc[i] = 0.f;
        warp_gemm3(sb + OFF_R2, sb + OFF_R1, m0, n0, lane, acc);
        float* ob = adj_out + (size_t)b * Nn * Nn;
        #pragma unroll
        for (int mf = 0; mf < 2; mf++)
            #pragma unroll
            for (int nf = 0; nf < 4; nf++) {
                const float* c4 = acc + (mf * 4 + nf) * 4;
                int r = m0 + mf * 16 + gid, c = n0 + nf * 8 + tig * 2;
                *(float2*)(ob + r * Nn + c)       = make_float2(c4[0], c4[1]);
                *(float2*)(ob + (r + 8) * Nn + c) = make_float2(c4[2], c4[3]);
            }
    }

    // ---- emb = S^T @ x, two 128-wide d halves ----
    for (int h = 0; h < 2; h++) {
        __syncthreads();   // prior stage readers done (GEMM2 consumed Ut, not stage)
        {
            const float4* x4 = (const float4*)x_b;
            for (int p = tid; p < Nn * 32; p += NT) {
                int r = p >> 5, q = p & 31;
                float4 v = x4[r * 64 + h * 32 + q];
                float* d = stage + r * PAD + q * 4;
                d[0] = v.x; d[1] = v.y; d[2] = v.z; d[3] = v.w;
            }
        }
        __syncthreads();
        for (int p = tid; p < 8192; p += NT) {
            int r = p >> 6, c = (p & 63) * 2;   // xt[r][c] = x[c][h*128 + r]
            uint32_t hh, ll;
            split_pair(stage[c * PAD + r], stage[(c + 1) * PAD + r], hh, ll);
            uint32_t off = (uint32_t)r * STRB + (uint32_t)c * 2;
            *(uint32_t*)(smc + OFF_R1 + off)         = hh;
            *(uint32_t*)(smc + OFF_R1 + TILEB + off) = ll;
        }
        __syncthreads();

        float acc[32];
        #pragma unroll
        for (int i = 0; i < 32; i++) acc[i] = 0.f;
        warp_gemm3(sb + OFF_R2, sb + OFF_R1, m0, n0, lane, acc);
        float* ob = emb_out + (size_t)b * Nn * Dd + h * 128;
        #pragma unroll
        for (int mf = 0; mf < 2; mf++)
            #pragma unroll
            for (int nf = 0; nf < 4; nf++) {
                const float* c4 = acc + (mf * 4 + nf) * 4;
                int r = m0 + mf * 16 + gid, c = n0 + nf * 8 + tig * 2;
                *(float2*)(ob + r * Dd + c)       = make_float2(c4[0], c4[1]);
                *(float2*)(ob + (r + 8) * Dd + c) = make_float2(c4[2], c4[3]);
            }
    }
}

extern "C" void kernel_launch(void* const* d_in, const int* in_sizes, int n_in,
                              void* d_out, int out_size) {
    const float* x    = (const float*)d_in[0];
    const float* adj  = (const float*)d_in[1];
    const int*   head = (const int*)d_in[2];
    const float* w    = (const float*)d_in[3];
    const float* bias = (const float*)d_in[4];

    float* out  = (float*)d_out;
    float* emb  = out;
    float* nadj = out + (size_t)Bb * Nn * Dd;

    cudaFuncSetAttribute(graph_enc_tc,
                         cudaFuncAttributeMaxDynamicSharedMemorySize, SMEM_BYTES);
    graph_enc_tc<<<Bb, NT, SMEM_BYTES>>>(x, adj, head, w, bias, emb, nadj);
}

// round 13
// speedup vs baseline: 3.7564x; 1.0879x over previous
#include <cuda_runtime.h>
#include <cuda_bf16.h>
#include <cstdint>

#define Nn 128
#define Dd 256
#define Tt 512
#define NT 256
#define Bb 512

#define QSTR 272              // bytes per row, Q tiles [m][k] (128 bf16 + 8 pad)
#define QTB  34816            // 128*272 per (hi|lo)
#define BSTR 272              // At / x chunk stride ([k=64][n=128])
#define WSTR 144              // W chunk stride ([m=128][k=64])
#define BCHB 18432            // chunk buffer bytes per (hi|lo): max(64*272,128*144)

// ---- smem byte offsets ----
#define OFF_WV   0            // 256 f
#define OFF_D    1024
#define OFF_MK   1536
#define OFF_T    2048
#define OFF_AL   2560
#define OFF_DC   3072
#define OFF_MISC 3584
#define OFF_PRES 3600         // 128 int
#define OFF_Q    4352         // Q hi
#define OFF_QLO  (OFF_Q + QTB)          // 39168
#define OFF_B    (OFF_Q + 2*QTB)        // 73984 chunk hi
#define OFF_BLO  (OFF_B + BCHB)         // 92416
#define SMEM_BYTES (OFF_B + 2*BCHB)     // 110848

// gmem scratch for the W = Q*A intermediate (sanctioned __device__ global)
__device__ float g_W[(size_t)Bb * Nn * Nn];

// ---------------- helpers ----------------
__device__ __forceinline__ uint32_t smem_u32(const void* p) {
    uint32_t a;
    asm("{ .reg .u64 t; cvta.to.shared.u64 t, %1; cvt.u32.u64 %0, t; }" : "=r"(a) : "l"(p));
    return a;
}
__device__ __forceinline__ void ldsm4(uint32_t* r, uint32_t addr) {
    asm volatile("ldmatrix.sync.aligned.m8n8.x4.shared.b16 {%0,%1,%2,%3}, [%4];"
        : "=r"(r[0]), "=r"(r[1]), "=r"(r[2]), "=r"(r[3]) : "r"(addr));
}
__device__ __forceinline__ void ldsm4t(uint32_t* r, uint32_t addr) {
    asm volatile("ldmatrix.sync.aligned.m8n8.x4.trans.shared.b16 {%0,%1,%2,%3}, [%4];"
        : "=r"(r[0]), "=r"(r[1]), "=r"(r[2]), "=r"(r[3]) : "r"(addr));
}
__device__ __forceinline__ void mma_bf16(float* d, const uint32_t* a, const uint32_t* b) {
    asm volatile(
        "mma.sync.aligned.m16n8k16.row.col.f32.bf16.bf16.f32 "
        "{%0,%1,%2,%3}, {%4,%5,%6,%7}, {%8,%9}, {%0,%1,%2,%3};"
        : "+f"(d[0]), "+f"(d[1]), "+f"(d[2]), "+f"(d[3])
        : "r"(a[0]), "r"(a[1]), "r"(a[2]), "r"(a[3]), "r"(b[0]), "r"(b[1]));
}
__device__ __forceinline__ void split_pair(float v0, float v1, uint32_t& h, uint32_t& l) {
    __nv_bfloat16 h0 = __float2bfloat16(v0);
    __nv_bfloat16 h1 = __float2bfloat16(v1);
    __nv_bfloat16 l0 = __float2bfloat16(v0 - __bfloat162float(h0));
    __nv_bfloat16 l1 = __float2bfloat16(v1 - __bfloat162float(h1));
    h = (uint32_t)__bfloat16_as_ushort(h0) | ((uint32_t)__bfloat16_as_ushort(h1) << 16);
    l = (uint32_t)__bfloat16_as_ushort(l0) | ((uint32_t)__bfloat16_as_ushort(l1) << 16);
}

// One K=64 chunk of a 3-term-split GEMM. Warp tile 32x64.
// A: [m][k] row-major hi/lo (normal ldsm). B: BT=1 -> natural [k][n] (trans ldsm,
// chunk-local k); BT=0 -> [n][k] row-major stride 272 (normal ldsm, bK0 k-byte base).
template<int BT>
__device__ __forceinline__ void gemm_chunk(
    uint32_t aHi, uint32_t aLo, int aStride, int aK0,
    uint32_t bHi, uint32_t bLo, int bK0,
    int m0, int n0, int lane, float* acc)
{
    #pragma unroll
    for (int ks = 0; ks < 4; ks++) {
        uint32_t Ah0[4], Ah1[4], Al0[4], Al1[4];
        {
            int ka = aK0 + ks * 32 + ((lane >> 4) << 4);
            uint32_t off = (uint32_t)((m0 + (lane & 15)) * aStride + ka);
            ldsm4(Ah0, aHi + off);
            ldsm4(Ah1, aHi + off + 16u * aStride);
            ldsm4(Al0, aLo + off);
            ldsm4(Al1, aLo + off + 16u * aStride);
        }
        #pragma unroll
        for (int j = 0; j < 4; j++) {
            uint32_t Bh[4], Bl[4];
            if (BT) {
                int row = ks * 16 + ((lane >> 3) & 1) * 8 + (lane & 7);
                int col = n0 + j * 16 + (lane >> 4) * 8;
                uint32_t off = (uint32_t)(row * BSTR + col * 2);
                ldsm4t(Bh, bHi + off);
                ldsm4t(Bl, bLo + off);
            } else {
                int brow = n0 + j * 16 + (lane & 7) + ((lane >> 4) << 3);
                int kb = bK0 + ks * 32 + (((lane >> 3) & 1) << 4);
                uint32_t off = (uint32_t)(brow * QSTR + kb);
                ldsm4(Bh, bHi + off);
                ldsm4(Bl, bLo + off);
            }
            #pragma unroll
            for (int sub = 0; sub < 2; sub++) {
                #pragma unroll
                for (int mf = 0; mf < 2; mf++) {
                    float* c = acc + (mf * 8 + j * 2 + sub) * 4;
                    const uint32_t* Ahm = mf ? Ah1 : Ah0;
                    const uint32_t* Alm = mf ? Al1 : Al0;
                    mma_bf16(c, Ahm, Bh + 2 * sub);
                    mma_bf16(c, Ahm, Bl + 2 * sub);
                    mma_bf16(c, Alm, Bh + 2 * sub);
                }
            }
        }
    }
}

__global__ __launch_bounds__(NT, 2)
void graph_enc_tc2(const float* __restrict__ x_g,
                   const float* __restrict__ adj_g,
                   const int*   __restrict__ head_g,
                   const float* __restrict__ w_g,
                   const float* __restrict__ bias_g,
                   float* __restrict__ emb_out,
                   float* __restrict__ adj_out)
{
    const int b = blockIdx.x;
    extern __shared__ char smc[];
    const uint32_t sb = smem_u32(smc);

    float* wv   = (float*)(smc + OFF_WV);
    float* dv   = (float*)(smc + OFF_D);
    float* mk   = (float*)(smc + OFF_MK);
    float* tv   = (float*)(smc + OFF_T);
    float* al   = (float*)(smc + OFF_AL);
    float* dc   = (float*)(smc + OFF_DC);
    float* misc = (float*)(smc + OFF_MISC);
    int*   pres = (int*)(smc + OFF_PRES);

    const int tid  = threadIdx.x;
    const int lane = tid & 31;
    const int wid  = tid >> 5;               // 8 warps
    const int m0   = (wid >> 1) * 32;        // 4x2 warp grid, tile 32x64
    const int n0   = (wid & 1) * 64;
    const int gid  = lane >> 2;
    const int tig  = lane & 3;

    const float* adj_b = adj_g + (size_t)b * Nn * Nn;
    const float* x_b   = x_g   + (size_t)b * Nn * Dd;
    float*       wscr  = g_W   + (size_t)b * Nn * Nn;

    // ---- init ----
    if (tid < Dd) wv[tid] = w_g[tid];
    if (tid < Nn) pres[tid] = 0;
    __syncthreads();

    // presence (T = 2*NT)
    pres[head_g[(size_t)b * Tt + tid]] = 1;
    pres[head_g[(size_t)b * Tt + tid + NT]] = 1;

    // ---- row sums -> dv, mk (warp w owns rows 16w..16w+15, adj from gmem) ----
    for (int rr = 0; rr < 16; rr++) {
        int i = wid * 16 + rr;
        const float* row = adj_b + i * Nn;
        float s = row[lane] + row[lane + 32] + row[lane + 64] + row[lane + 96];
        #pragma unroll
        for (int o = 16; o; o >>= 1) s += __shfl_xor_sync(0xffffffffu, s, o);
        if (lane == 0) {
            float deg = s + 1.0f;
            if (deg < 1.0f) deg = 1.0f;
            dv[i] = rsqrtf(deg);
            mk[i] = (s > 0.0f) ? 1.0f : 0.0f;
        }
    }
    __syncthreads();

    // ---- t_i = (x_i . w) * d_i ----
    for (int rr = 0; rr < 16; rr++) {
        int i = wid * 16 + rr;
        const float* xr = x_b + (size_t)i * Dd;
        float s = 0.f;
        #pragma unroll
        for (int j = lane; j < Dd; j += 32) s += xr[j] * wv[j];
        #pragma unroll
        for (int o = 16; o; o >>= 1) s += __shfl_xor_sync(0xffffffffu, s, o);
        if (lane == 0) tv[i] = s * dv[i];
    }
    __syncthreads();

    // ---- alpha ----
    {
        float bias = __ldg(bias_g);
        for (int rr = 0; rr < 16; rr++) {
            int i = wid * 16 + rr;
            const float* row = adj_b + i * Nn;
            float s = 0.f;
            #pragma unroll
            for (int j = lane; j < Nn; j += 32) s += row[j] * tv[j];
            #pragma unroll
            for (int o = 16; o; o >>= 1) s += __shfl_xor_sync(0xffffffffu, s, o);
            if (lane == 0) {
                float z  = mk[i] * dv[i] * (s + tv[i]) + bias;
                float zz = z * z;
                al[i] = 1.0f / (1.0f + expf(-zz));
            }
        }
    }
    __syncthreads();

    // ---- unique count -> idx, use_cut ----
    if (wid == 0) {
        int c = pres[lane] + pres[lane + 32] + pres[lane + 64] + pres[lane + 96];
        #pragma unroll
        for (int o = 16; o; o >>= 1) c += __shfl_xor_sync(0xffffffffu, c, o);
        if (lane == 0) {
            int k = (int)ceilf((float)c * 0.1f) + 1;
            int idx = k - 1;
            if (idx > Nn - 1) idx = Nn - 1;
            if (idx < 0) idx = 0;
            misc[0] = (float)idx;
            misc[1] = (c > 1) ? 1.0f : 0.0f;
        }
    }
    __syncthreads();

    // ---- rank-select cut (tie-correct) ----
    if (tid < Nn) {
        float a = al[tid];
        int rk = 0, eq = 0;
        #pragma unroll 4
        for (int j = 0; j < Nn; j++) {
            float aj = al[j];
            rk += (aj > a);
            eq += (aj == a);
        }
        int idx = (int)misc[0];
        if (rk <= idx && idx < rk + eq) misc[2] = a;
    }
    __syncthreads();

    // ---- dc_j ----
    if (tid < Nn) {
        float cut = (misc[1] != 0.0f) ? misc[2] : 0.0f;
        float ca = al[tid] + 1e-7f - cut;
        if (ca < 0.f) ca = 0.f;
        dc[tid] = ca * dv[tid];
    }
    __syncthreads();

    // ---- S row-scale -> tv (overwrite; S_ij = tv[i]*(A+I)_ij*dc[j]) ----
    for (int rr = 0; rr < 16; rr++) {
        int i = wid * 16 + rr;
        const float* row = adj_b + i * Nn;
        float s = 0.f;
        #pragma unroll
        for (int j = lane; j < Nn; j += 32) {
            float a = row[j] + ((i == j) ? 1.0f : 0.0f);
            s += a * dc[j];
        }
        #pragma unroll
        for (int o = 16; o; o >>= 1) s += __shfl_xor_sync(0xffffffffu, s, o);
        if (lane == 0) {
            float md  = mk[i] * dv[i];
            float den = md * s;
            if (den < 1e-12f) den = 1e-12f;
            tv[i] = md / den;
        }
    }
    __syncthreads();

    // ---- build Q[m][k] = (A[k][m] + (k==m)) * tv[k]  (hi/lo, STS.128) ----
    for (int item = wid; item < 64; item += 8) {
        int kb = (item >> 2) * 8;           // 16 k-blocks of 8
        int m  = (item & 3) * 32 + lane;    // 4 m-blocks of 32
        float v[8];
        #pragma unroll
        for (int j = 0; j < 8; j++) {
            int k = kb + j;
            float a = adj_b[k * Nn + m] + ((k == m) ? 1.0f : 0.0f);
            v[j] = a * tv[k];
        }
        uint4 H, L;
        split_pair(v[0], v[1], H.x, L.x);
        split_pair(v[2], v[3], H.y, L.y);
        split_pair(v[4], v[5], H.z, L.z);
        split_pair(v[6], v[7], H.w, L.w);
        uint32_t off = (uint32_t)(m * QSTR + kb * 2);
        *(uint4*)(smc + OFF_Q   + off) = H;
        *(uint4*)(smc + OFF_QLO + off) = L;
    }

    // ================= GEMM_w: W = Q * A  -> gmem scratch =================
    float acc[64];
    #pragma unroll
    for (int i = 0; i < 64; i++) acc[i] = 0.f;

    for (int c = 0; c < 2; c++) {
        __syncthreads();     // also covers Q-build completion at c==0
        // build At chunk: natural A rows 64c..64c+63 (copy + split)
        for (int p = tid; p < 2048; p += NT) {
            int row = p >> 5, q = p & 31;
            float4 v = ((const float4*)(adj_b + (c * 64 + row) * Nn))[q];
            uint32_t h0, l0, h1, l1;
            split_pair(v.x, v.y, h0, l0);
            split_pair(v.z, v.w, h1, l1);
            uint32_t off = (uint32_t)(row * BSTR + q * 8);
            *(uint2*)(smc + OFF_B   + off) = make_uint2(h0, h1);
            *(uint2*)(smc + OFF_BLO + off) = make_uint2(l0, l1);
        }
        __syncthreads();
        gemm_chunk<1>(sb + OFF_Q, sb + OFF_QLO, QSTR, c * 128,
                      sb + OFF_B, sb + OFF_BLO, 0, m0, n0, lane, acc);
    }
    // W epilogue -> gmem scratch (fp32)
    #pragma unroll
    for (int mf = 0; mf < 2; mf++)
        #pragma unroll
        for (int j8 = 0; j8 < 8; j8++) {
            const float* c4 = acc + (mf * 8 + j8) * 4;
            int r = m0 + mf * 16 + gid, cc = n0 + j8 * 8 + tig * 2;
            *(float2*)(wscr + r * Nn + cc)       = make_float2(c4[0], c4[1]);
            *(float2*)(wscr + (r + 8) * Nn + cc) = make_float2(c4[2], c4[3]);
        }

    // ================= GEMM_f: F = W * Q^T -> new_adj =================
    #pragma unroll
    for (int i = 0; i < 64; i++) acc[i] = 0.f;
    for (int c = 0; c < 2; c++) {
        __syncthreads();     // orders scratch writes (c==0) / prior mma reads
        // build W chunk [m=128][k=64] from scratch (natural, coalesced)
        for (int p = tid; p < 2048; p += NT) {
            int row = p >> 4, q = p & 15;
            float4 v = ((const float4*)(wscr + row * Nn + c * 64))[q];
            uint32_t h0, l0, h1, l1;
            split_pair(v.x, v.y, h0, l0);
            split_pair(v.z, v.w, h1, l1);
            uint32_t off = (uint32_t)(row * WSTR + q * 8);
            *(uint2*)(smc + OFF_B   + off) = make_uint2(h0, h1);
            *(uint2*)(smc + OFF_BLO + off) = make_uint2(l0, l1);
        }
        __syncthreads();
        gemm_chunk<0>(sb + OFF_B, sb + OFF_BLO, WSTR, 0,
                      sb + OFF_Q, sb + OFF_QLO, c * 128, m0, n0, lane, acc);
    }
    // new_adj[m][n] = dc[m] * F[m][n] * dc[n]
    {
        float* ob = adj_out + (size_t)b * Nn * Nn;
        #pragma unroll
        for (int mf = 0; mf < 2; mf++)
            #pragma unroll
            for (int j8 = 0; j8 < 8; j8++) {
                const float* c4 = acc + (mf * 8 + j8) * 4;
                int r = m0 + mf * 16 + gid, cc = n0 + j8 * 8 + tig * 2;
                float dr0 = dc[r], dr1 = dc[r + 8];
                float dc0 = dc[cc], dc1 = dc[cc + 1];
                *(float2*)(ob + r * Nn + cc) =
                    make_float2(c4[0] * dr0 * dc0, c4[1] * dr0 * dc1);
                *(float2*)(ob + (r + 8) * Nn + cc) =
                    make_float2(c4[2] * dr1 * dc0, c4[3] * dr1 * dc1);
            }
    }

    // ================= GEMM_e: emb = dc * (Q * x), two D halves =================
    for (int h = 0; h < 2; h++) {
        #pragma unroll
        for (int i = 0; i < 64; i++) acc[i] = 0.f;
        for (int c = 0; c < 2; c++) {
            __syncthreads();
            // build x chunk: natural x rows 64c..64c+63, cols h*128..+127
            for (int p = tid; p < 2048; p += NT) {
                int row = p >> 5, q = p & 31;
                float4 v = ((const float4*)(x_b + (size_t)(c * 64 + row) * Dd + h * 128))[q];
                uint32_t h0, l0, h1, l1;
                split_pair(v.x, v.y, h0, l0);
                split_pair(v.z, v.w, h1, l1);
                uint32_t off = (uint32_t)(row * BSTR + q * 8);
                *(uint2*)(smc + OFF_B   + off) = make_uint2(h0, h1);
                *(uint2*)(smc + OFF_BLO + off) = make_uint2(l0, l1);
            }
            __syncthreads();
            gemm_chunk<1>(sb + OFF_Q, sb + OFF_QLO, QSTR, c * 128,
                          sb + OFF_B, sb + OFF_BLO, 0, m0, n0, lane, acc);
        }
        float* ob = emb_out + (size_t)b * Nn * Dd + h * 128;
        #pragma unroll
        for (int mf = 0; mf < 2; mf++)
            #pragma unroll
            for (int j8 = 0; j8 < 8; j8++) {
                const float* c4 = acc + (mf * 8 + j8) * 4;
                int r = m0 + mf * 16 + gid, cc = n0 + j8 * 8 + tig * 2;
                float dr0 = dc[r], dr1 = dc[r + 8];
                *(float2*)(ob + r * Dd + cc)       = make_float2(c4[0] * dr0, c4[1] * dr0);
                *(float2*)(ob + (r + 8) * Dd + cc) = make_float2(c4[2] * dr1, c4[3] * dr1);
            }
    }
}

extern "C" void kernel_launch(void* const* d_in, const int* in_sizes, int n_in,
                              void* d_out, int out_size) {
    const float* x    = (const float*)d_in[0];
    const float* adj  = (const float*)d_in[1];
    const int*   head = (const int*)d_in[2];
    const float* w    = (const float*)d_in[3];
    const float* bias = (const float*)d_in[4];

    float* out  = (float*)d_out;
    float* emb  = out;
    float* nadj = out + (size_t)Bb * Nn * Dd;

    cudaFuncSetAttribute(graph_enc_tc2,
                         cudaFuncAttributeMaxDynamicSharedMemorySize, SMEM_BYTES);
    graph_enc_tc2<<<Bb, NT, SMEM_BYTES>>>(x, adj, head, w, bias, emb, nadj);
}

// round 17
// speedup vs baseline: 3.9077x; 1.0403x over previous
#include <cuda_runtime.h>
#include <cuda_bf16.h>
#include <cstdint>

#define Nn 128
#define Dd 256
#define Tt 512
#define NT 256
#define Bb 512

#define QSTR 272              // Q row stride bytes ([m][k] 128 bf16 + pad)
#define QTB  34816            // 128*272 per (hi|lo)
#define CSTR 272              // trans-chunk row stride ([k=32][n=128])
#define WCSTR 48              // W-chunk row stride ([m=128][k=16] 32B + 16 pad)
#define SLOT 8704             // stage slot bytes per (hi|lo): 32*272

// ---- smem byte offsets ----
#define OFF_WV   0
#define OFF_D    1024
#define OFF_MK   1536
#define OFF_T    2048
#define OFF_AL   2560
#define OFF_DC   3072
#define OFF_MISC 3584
#define OFF_PRES 3600
#define OFF_Q    4352
#define OFF_QLO  (OFF_Q + QTB)
#define OFF_B    (OFF_Q + 2*QTB)          // 73984: 2 stages x (hi|lo)
#define SMEM_BYTES (OFF_B + 4*SLOT)       // 108800

#define STGHI(s) (OFF_B + (s)*2*SLOT)
#define STGLO(s) (STGHI(s) + SLOT)

// gmem scratch for W = Q*A (sanctioned __device__ global)
__device__ float g_W[(size_t)Bb * Nn * Nn];

// ---------------- helpers ----------------
__device__ __forceinline__ uint32_t smem_u32(const void* p) {
    uint32_t a;
    asm("{ .reg .u64 t; cvta.to.shared.u64 t, %1; cvt.u32.u64 %0, t; }" : "=r"(a) : "l"(p));
    return a;
}
__device__ __forceinline__ void ldsm4(uint32_t* r, uint32_t addr) {
    asm volatile("ldmatrix.sync.aligned.m8n8.x4.shared.b16 {%0,%1,%2,%3}, [%4];"
        : "=r"(r[0]), "=r"(r[1]), "=r"(r[2]), "=r"(r[3]) : "r"(addr));
}
__device__ __forceinline__ void ldsm4t(uint32_t* r, uint32_t addr) {
    asm volatile("ldmatrix.sync.aligned.m8n8.x4.trans.shared.b16 {%0,%1,%2,%3}, [%4];"
        : "=r"(r[0]), "=r"(r[1]), "=r"(r[2]), "=r"(r[3]) : "r"(addr));
}
__device__ __forceinline__ void mma_bf16(float* d, const uint32_t* a, const uint32_t* b) {
    asm volatile(
        "mma.sync.aligned.m16n8k16.row.col.f32.bf16.bf16.f32 "
        "{%0,%1,%2,%3}, {%4,%5,%6,%7}, {%8,%9}, {%0,%1,%2,%3};"
        : "+f"(d[0]), "+f"(d[1]), "+f"(d[2]), "+f"(d[3])
        : "r"(a[0]), "r"(a[1]), "r"(a[2]), "r"(a[3]), "r"(b[0]), "r"(b[1]));
}
__device__ __forceinline__ void split_pair(float v0, float v1, uint32_t& h, uint32_t& l) {
    __nv_bfloat16 h0 = __float2bfloat16(v0);
    __nv_bfloat16 h1 = __float2bfloat16(v1);
    __nv_bfloat16 l0 = __float2bfloat16(v0 - __bfloat162float(h0));
    __nv_bfloat16 l1 = __float2bfloat16(v1 - __bfloat162float(h1));
    h = (uint32_t)__bfloat16_as_ushort(h0) | ((uint32_t)__bfloat16_as_ushort(h1) << 16);
    l = (uint32_t)__bfloat16_as_ushort(l0) | ((uint32_t)__bfloat16_as_ushort(l1) << 16);
}

// one K-chunk of a 3-term-split GEMM; warp tile 32x64.
// A: [m][k] bf16 hi/lo, normal ldsm, stride aStride, k-byte base aK0.
// B: BT=1 -> natural [k][n] chunk (trans ldsm, chunk-local k, stride 272);
//    BT=0 -> Q [n][k] (normal ldsm, stride 272, k-byte base bK0).
template<int BT, int NKS>
__device__ __forceinline__ void gemm_chunk(
    uint32_t aHi, uint32_t aLo, int aStride, int aK0,
    uint32_t bHi, uint32_t bLo, int bK0,
    int m0, int n0, int lane, float* acc)
{
    #pragma unroll
    for (int ks = 0; ks < NKS; ks++) {
        uint32_t Ah0[4], Ah1[4], Al0[4], Al1[4];
        {
            int ka = aK0 + ks * 32 + ((lane >> 4) << 4);
            uint32_t off = (uint32_t)((m0 + (lane & 15)) * aStride + ka);
            ldsm4(Ah0, aHi + off);
            ldsm4(Ah1, aHi + off + 16u * aStride);
            ldsm4(Al0, aLo + off);
            ldsm4(Al1, aLo + off + 16u * aStride);
        }
        #pragma unroll
        for (int j = 0; j < 4; j++) {
            uint32_t Bh[4], Bl[4];
            if (BT) {
                int row = ks * 16 + ((lane >> 3) & 1) * 8 + (lane & 7);
                int col = n0 + j * 16 + (lane >> 4) * 8;
                uint32_t off = (uint32_t)(row * CSTR + col * 2);
                ldsm4t(Bh, bHi + off);
                ldsm4t(Bl, bLo + off);
            } else {
                int brow = n0 + j * 16 + (lane & 7) + ((lane >> 4) << 3);
                int kb = bK0 + ks * 32 + (((lane >> 3) & 1) << 4);
                uint32_t off = (uint32_t)(brow * QSTR + kb);
                ldsm4(Bh, bHi + off);
                ldsm4(Bl, bLo + off);
            }
            #pragma unroll
            for (int sub = 0; sub < 2; sub++) {
                #pragma unroll
                for (int mf = 0; mf < 2; mf++) {
                    float* c = acc + (mf * 8 + j * 2 + sub) * 4;
                    const uint32_t* Ahm = mf ? Ah1 : Ah0;
                    const uint32_t* Alm = mf ? Al1 : Al0;
                    mma_bf16(c, Ahm, Bh + 2 * sub);
                    mma_bf16(c, Ahm, Bl + 2 * sub);
                    mma_bf16(c, Alm, Bh + 2 * sub);
                }
            }
        }
    }
}

// prefetch 32 rows x 128 cols fp32 (4 float4/thread)
__device__ __forceinline__ void pf_rows(const float* src, int ld, float4* pre, int tid) {
    #pragma unroll
    for (int i = 0; i < 4; i++) {
        int p = tid + i * 256, row = p >> 5, q = p & 31;
        pre[i] = ((const float4*)(src + (size_t)row * ld))[q];
    }
}
__device__ __forceinline__ void st_chunk1(const float4* pre, char* smc, int slot, int tid) {
    #pragma unroll
    for (int i = 0; i < 4; i++) {
        int p = tid + i * 256, row = p >> 5, q = p & 31;
        uint32_t h0, l0, h1, l1;
        split_pair(pre[i].x, pre[i].y, h0, l0);
        split_pair(pre[i].z, pre[i].w, h1, l1);
        uint32_t off = (uint32_t)(row * CSTR + q * 8);
        *(uint2*)(smc + STGHI(slot) + off) = make_uint2(h0, h1);
        *(uint2*)(smc + STGLO(slot) + off) = make_uint2(l0, l1);
    }
}
// prefetch W chunk 128 rows x 16 cols (2 float4/thread)
__device__ __forceinline__ void pf_w(const float* wscr, int c, float4* pre, int tid) {
    #pragma unroll
    for (int i = 0; i < 2; i++) {
        int p = tid + i * 256, row = p >> 2, q = p & 3;
        pre[i] = ((const float4*)(wscr + row * Nn + c * 16))[q];
    }
}
__device__ __forceinline__ void st_w(const float4* pre, char* smc, int slot, int tid) {
    #pragma unroll
    for (int i = 0; i < 2; i++) {
        int p = tid + i * 256, row = p >> 2, q = p & 3;
        uint32_t h0, l0, h1, l1;
        split_pair(pre[i].x, pre[i].y, h0, l0);
        split_pair(pre[i].z, pre[i].w, h1, l1);
        uint32_t off = (uint32_t)(row * WCSTR + q * 8);
        *(uint2*)(smc + STGHI(slot) + off) = make_uint2(h0, h1);
        *(uint2*)(smc + STGLO(slot) + off) = make_uint2(l0, l1);
    }
}

__global__ __launch_bounds__(NT, 2)
void graph_enc_tc3(const float* __restrict__ x_g,
                   const float* __restrict__ adj_g,
                   const int*   __restrict__ head_g,
                   const float* __restrict__ w_g,
                   const float* __restrict__ bias_g,
                   float* __restrict__ emb_out,
                   float* __restrict__ adj_out)
{
    const int b = blockIdx.x;
    extern __shared__ char smc[];
    const uint32_t sb = smem_u32(smc);

    float* wv   = (float*)(smc + OFF_WV);
    float* dv   = (float*)(smc + OFF_D);
    float* mk   = (float*)(smc + OFF_MK);
    float* tv   = (float*)(smc + OFF_T);
    float* al   = (float*)(smc + OFF_AL);
    float* dc   = (float*)(smc + OFF_DC);
    float* misc = (float*)(smc + OFF_MISC);
    int*   pres = (int*)(smc + OFF_PRES);

    const int tid  = threadIdx.x;
    const int lane = tid & 31;
    const int wid  = tid >> 5;               // 8 warps
    const int m0   = (wid >> 1) * 32;        // 4x2 warp grid, tile 32x64
    const int n0   = (wid & 1) * 64;
    const int gid  = lane >> 2;
    const int tig  = lane & 3;

    const float* adj_b = adj_g + (size_t)b * Nn * Nn;
    const float* x_b   = x_g   + (size_t)b * Nn * Dd;
    float*       wscr  = g_W   + (size_t)b * Nn * Nn;

    const uint32_t QHI = sb + OFF_Q, QLO = sb + OFF_QLO;

    // ---- init ----
    if (tid < Dd) wv[tid] = w_g[tid];
    if (tid < Nn) pres[tid] = 0;
    __syncthreads();

    pres[head_g[(size_t)b * Tt + tid]] = 1;
    pres[head_g[(size_t)b * Tt + tid + NT]] = 1;

    // ---- row sums -> dv, mk ----
    for (int rr = 0; rr < 16; rr++) {
        int i = wid * 16 + rr;
        const float* row = adj_b + i * Nn;
        float s = row[lane] + row[lane + 32] + row[lane + 64] + row[lane + 96];
        #pragma unroll
        for (int o = 16; o; o >>= 1) s += __shfl_xor_sync(0xffffffffu, s, o);
        if (lane == 0) {
            float deg = s + 1.0f;
            if (deg < 1.0f) deg = 1.0f;
            dv[i] = rsqrtf(deg);
            mk[i] = (s > 0.0f) ? 1.0f : 0.0f;
        }
    }
    __syncthreads();

    // ---- t_i = (x_i . w) * d_i ----
    for (int rr = 0; rr < 16; rr++) {
        int i = wid * 16 + rr;
        const float* xr = x_b + (size_t)i * Dd;
        float s = 0.f;
        #pragma unroll
        for (int j = lane; j < Dd; j += 32) s += xr[j] * wv[j];
        #pragma unroll
        for (int o = 16; o; o >>= 1) s += __shfl_xor_sync(0xffffffffu, s, o);
        if (lane == 0) tv[i] = s * dv[i];
    }
    __syncthreads();

    // ---- alpha ----
    {
        float bias = __ldg(bias_g);
        for (int rr = 0; rr < 16; rr++) {
            int i = wid * 16 + rr;
            const float* row = adj_b + i * Nn;
            float s = 0.f;
            #pragma unroll
            for (int j = lane; j < Nn; j += 32) s += row[j] * tv[j];
            #pragma unroll
            for (int o = 16; o; o >>= 1) s += __shfl_xor_sync(0xffffffffu, s, o);
            if (lane == 0) {
                float z  = mk[i] * dv[i] * (s + tv[i]) + bias;
                float zz = z * z;
                al[i] = 1.0f / (1.0f + expf(-zz));
            }
        }
    }
    __syncthreads();

    // ---- unique count ----
    if (wid == 0) {
        int c = pres[lane] + pres[lane + 32] + pres[lane + 64] + pres[lane + 96];
        #pragma unroll
        for (int o = 16; o; o >>= 1) c += __shfl_xor_sync(0xffffffffu, c, o);
        if (lane == 0) {
            int k = (int)ceilf((float)c * 0.1f) + 1;
            int idx = k - 1;
            if (idx > Nn - 1) idx = Nn - 1;
            if (idx < 0) idx = 0;
            misc[0] = (float)idx;
            misc[1] = (c > 1) ? 1.0f : 0.0f;
        }
    }
    __syncthreads();

    // ---- rank-select cut ----
    if (tid < Nn) {
        float a = al[tid];
        int rk = 0, eq = 0;
        #pragma unroll 4
        for (int j = 0; j < Nn; j++) {
            float aj = al[j];
            rk += (aj > a);
            eq += (aj == a);
        }
        int idx = (int)misc[0];
        if (rk <= idx && idx < rk + eq) misc[2] = a;
    }
    __syncthreads();

    // ---- dc_j ----
    if (tid < Nn) {
        float cut = (misc[1] != 0.0f) ? misc[2] : 0.0f;
        float ca = al[tid] + 1e-7f - cut;
        if (ca < 0.f) ca = 0.f;
        dc[tid] = ca * dv[tid];
    }
    __syncthreads();

    // ---- S row-scale -> tv ----
    for (int rr = 0; rr < 16; rr++) {
        int i = wid * 16 + rr;
        const float* row = adj_b + i * Nn;
        float s = 0.f;
        #pragma unroll
        for (int j = lane; j < Nn; j += 32) {
            float a = row[j] + ((i == j) ? 1.0f : 0.0f);
            s += a * dc[j];
        }
        #pragma unroll
        for (int o = 16; o; o >>= 1) s += __shfl_xor_sync(0xffffffffu, s, o);
        if (lane == 0) {
            float md  = mk[i] * dv[i];
            float den = md * s;
            if (den < 1e-12f) den = 1e-12f;
            tv[i] = md / den;
        }
    }
    __syncthreads();

    float4 pre[4];
    float acc[64];

    // ================= GEMM_w: W = Q * A -> scratch =================
    // prologue prefetch (overlaps Q build below)
    pf_rows(adj_b, Nn, pre, tid);

    // ---- build Q[m][k] = (A[k][m] + (k==m)) * tv[k] (hi/lo) ----
    for (int item = wid; item < 64; item += 8) {
        int kb = (item >> 2) * 8;
        int m  = (item & 3) * 32 + lane;
        float v[8];
        #pragma unroll
        for (int j = 0; j < 8; j++) {
            int k = kb + j;
            float a = adj_b[k * Nn + m] + ((k == m) ? 1.0f : 0.0f);
            v[j] = a * tv[k];
        }
        uint4 H, L;
        split_pair(v[0], v[1], H.x, L.x);
        split_pair(v[2], v[3], H.y, L.y);
        split_pair(v[4], v[5], H.z, L.z);
        split_pair(v[6], v[7], H.w, L.w);
        uint32_t off = (uint32_t)(m * QSTR + kb * 2);
        *(uint4*)(smc + OFF_Q   + off) = H;
        *(uint4*)(smc + OFF_QLO + off) = L;
    }
    st_chunk1(pre, smc, 0, tid);
    __syncthreads();

    #pragma unroll
    for (int i = 0; i < 64; i++) acc[i] = 0.f;
    #pragma unroll
    for (int c = 0; c < 4; c++) {
        if (c < 3) pf_rows(adj_b + (c + 1) * 32 * Nn, Nn, pre, tid);
        gemm_chunk<1, 2>(QHI, QLO, QSTR, c * 64,
                         sb + STGHI(c & 1), sb + STGLO(c & 1), 0, m0, n0, lane, acc);
        if (c < 3) st_chunk1(pre, smc, (c + 1) & 1, tid);
        __syncthreads();
    }
    // W epilogue -> gmem scratch
    #pragma unroll
    for (int mf = 0; mf < 2; mf++)
        #pragma unroll
        for (int j8 = 0; j8 < 8; j8++) {
            const float* c4 = acc + (mf * 8 + j8) * 4;
            int r = m0 + mf * 16 + gid, cc = n0 + j8 * 8 + tig * 2;
            *(float2*)(wscr + r * Nn + cc)       = make_float2(c4[0], c4[1]);
            *(float2*)(wscr + (r + 8) * Nn + cc) = make_float2(c4[2], c4[3]);
        }

    // ================= GEMM_e: emb = dc * (Q * x) (runs while W drains) ====
    for (int h = 0; h < 2; h++) {
        pf_rows(x_b + h * 128, Dd, pre, tid);
        st_chunk1(pre, smc, 0, tid);
        __syncthreads();
        #pragma unroll
        for (int i = 0; i < 64; i++) acc[i] = 0.f;
        #pragma unroll
        for (int c = 0; c < 4; c++) {
            if (c < 3) pf_rows(x_b + (size_t)(c + 1) * 32 * Dd + h * 128, Dd, pre, tid);
            gemm_chunk<1, 2>(QHI, QLO, QSTR, c * 64,
                             sb + STGHI(c & 1), sb + STGLO(c & 1), 0, m0, n0, lane, acc);
            if (c < 3) st_chunk1(pre, smc, (c + 1) & 1, tid);
            __syncthreads();
        }
        float* ob = emb_out + (size_t)b * Nn * Dd + h * 128;
        #pragma unroll
        for (int mf = 0; mf < 2; mf++)
            #pragma unroll
            for (int j8 = 0; j8 < 8; j8++) {
                const float* c4 = acc + (mf * 8 + j8) * 4;
                int r = m0 + mf * 16 + gid, cc = n0 + j8 * 8 + tig * 2;
                float dr0 = dc[r], dr1 = dc[r + 8];
                *(float2*)(ob + r * Dd + cc)       = make_float2(c4[0] * dr0, c4[1] * dr0);
                *(float2*)(ob + (r + 8) * Dd + cc) = make_float2(c4[2] * dr1, c4[3] * dr1);
            }
    }

    // ================= GEMM_f: F = W * Q^T -> new_adj =================
    {
        float4 prew[2];
        pf_w(wscr, 0, prew, tid);
        st_w(prew, smc, 0, tid);
        __syncthreads();
        #pragma unroll
        for (int i = 0; i < 64; i++) acc[i] = 0.f;
        #pragma unroll
        for (int c = 0; c < 8; c++) {
            if (c < 7) pf_w(wscr, c + 1, prew, tid);
            gemm_chunk<0, 1>(sb + STGHI(c & 1), sb + STGLO(c & 1), WCSTR, 0,
                             QHI, QLO, c * 32, m0, n0, lane, acc);
            if (c < 7) st_w(prew, smc, (c + 1) & 1, tid);
            __syncthreads();
        }
        float* ob = adj_out + (size_t)b * Nn * Nn;
        #pragma unroll
        for (int mf = 0; mf < 2; mf++)
            #pragma unroll
            for (int j8 = 0; j8 < 8; j8++) {
                const float* c4 = acc + (mf * 8 + j8) * 4;
                int r = m0 + mf * 16 + gid, cc = n0 + j8 * 8 + tig * 2;
                float dr0 = dc[r], dr1 = dc[r + 8];
                float dc0 = dc[cc], dc1 = dc[cc + 1];
                *(float2*)(ob + r * Nn + cc) =
                    make_float2(c4[0] * dr0 * dc0, c4[1] * dr0 * dc1);
                *(float2*)(ob + (r + 8) * Nn + cc) =
                    make_float2(c4[2] * dr1 * dc0, c4[3] * dr1 * dc1);
            }
    }
}

extern "C" void kernel_launch(void* const* d_in, const int* in_sizes, int n_in,
                              void* d_out, int out_size) {
    const float* x    = (const float*)d_in[0];
    const float* adj  = (const float*)d_in[1];
    const int*   head = (const int*)d_in[2];
    const float* w    = (const float*)d_in[3];
    const float* bias = (const float*)d_in[4];

    float* out  = (float*)d_out;
    float* emb  = out;
    float* nadj = out + (size_t)Bb * Nn * Dd;

    cudaFuncSetAttribute(graph_enc_tc3,
                         cudaFuncAttributeMaxDynamicSharedMemorySize, SMEM_BYTES);
    graph_enc_tc3<<<Bb, NT, SMEM_BYTES>>>(x, adj, head, w, bias, emb, nadj);
}